// round 10
// baseline (speedup 1.0000x reference)
#include <cuda_runtime.h>
#include <cuda_fp16.h>
#include <cstdint>

#define BATCH 32768
#define HDIM  1024
#define NFAM  10

// ---------------------------------------------------------------- scratch
__device__ __align__(16) int     g_nearest[BATCH];
__device__ __align__(16) float   g_protoW1[NFAM * HDIM];
__device__ __align__(16) __half  g_feat[(size_t)BATCH * HDIM];
__device__ __align__(16) __half  g_hid[(size_t)BATCH * HDIM];
__device__ __align__(16) __half  g_w1t[HDIM * HDIM];    // transposed
__device__ __align__(16) __half  g_w2t[HDIM * HDIM];    // transposed

// ---------------------------------------------------------------- helpers
__device__ __forceinline__ uint32_t smem_u32(const void* p) {
    uint32_t a;
    asm("{ .reg .u64 t; cvta.to.shared.u64 t, %1; cvt.u32.u64 %0, t; }" : "=r"(a) : "l"(p));
    return a;
}
__device__ __forceinline__ void cp16(uint32_t dst, const void* src) {
    asm volatile("cp.async.cg.shared.global [%0], [%1], 16;" :: "r"(dst), "l"(src) : "memory");
}
#define CP_COMMIT() asm volatile("cp.async.commit_group;" ::: "memory")
#define CP_WAIT2()  asm volatile("cp.async.wait_group 2;"  ::: "memory")

__device__ __forceinline__ void ldsm4(uint32_t& r0, uint32_t& r1, uint32_t& r2, uint32_t& r3,
                                      uint32_t addr) {
    asm volatile("ldmatrix.sync.aligned.m8n8.x4.shared.b16 {%0,%1,%2,%3}, [%4];"
                 : "=r"(r0), "=r"(r1), "=r"(r2), "=r"(r3) : "r"(addr));
}
__device__ __forceinline__ void mma_f16(float* c, uint32_t a0, uint32_t a1, uint32_t a2,
                                        uint32_t a3, uint32_t b0, uint32_t b1) {
    asm volatile("mma.sync.aligned.m16n8k16.row.col.f32.f16.f16.f32 "
                 "{%0,%1,%2,%3}, {%4,%5,%6,%7}, {%8,%9}, {%0,%1,%2,%3};"
                 : "+f"(c[0]), "+f"(c[1]), "+f"(c[2]), "+f"(c[3])
                 : "r"(a0), "r"(a1), "r"(a2), "r"(a3), "r"(b0), "r"(b1));
}

// ---------------------------------------------------------------- fused prep
// Flat grid of 3112 blocks x 256 threads:
//   [0, 1024)     : argcvt  - feat -> fp16, nearest prototype (pp computed in-block)
//   [1024, 2048)  : tcvt W1 - transpose + fp16
//   [2048, 3072)  : tcvt W2 - transpose + fp16
//   [3072, 3112)  : protow1 - exact fp32 proto @ W1_bot + b1
__global__ __launch_bounds__(256) void prep_kernel(const float* __restrict__ feat,
                                                   const float* __restrict__ protos,
                                                   const float* __restrict__ W1,
                                                   const float* __restrict__ b1,
                                                   const float* __restrict__ W2) {
    __shared__ float4 sp4[NFAM * 256];   // 40 KB (argcvt); reused as fp32 tile by tcvt

    const int blk = blockIdx.x;

    if (blk < 1024) {
        // ---------------- argcvt ----------------
        for (int i = threadIdx.x; i < NFAM * 256; i += 256)
            sp4[i] = reinterpret_cast<const float4*>(protos)[i];
        __syncthreads();

        const int warp = threadIdx.x >> 5, lane = threadIdx.x & 31;
        const int row0 = (blk * 8 + warp) * 4;

        // pp[j] from smem (each thread partial, reduced with the dots below)
        float pp[NFAM];
#pragma unroll
        for (int j = 0; j < NFAM; ++j) pp[j] = 0.f;
        for (int t = 0; t < 8; ++t) {
            const int idx = lane + 32 * t;
#pragma unroll
            for (int j = 0; j < NFAM; ++j) {
                const float4 p = sp4[j * 256 + idx];
                pp[j] = fmaf(p.x, p.x, fmaf(p.y, p.y, fmaf(p.z, p.z, fmaf(p.w, p.w, pp[j]))));
            }
        }

        float dot[NFAM][4];
#pragma unroll
        for (int j = 0; j < NFAM; ++j)
#pragma unroll
            for (int r = 0; r < 4; ++r) dot[j][r] = 0.f;

        for (int t = 0; t < 8; ++t) {
            const int idx = lane + 32 * t;
            float4 fv[4];
#pragma unroll
            for (int r = 0; r < 4; ++r)
                fv[r] = reinterpret_cast<const float4*>(feat)[(size_t)(row0 + r) * 256 + idx];

#pragma unroll
            for (int r = 0; r < 4; ++r) {
                __half2 h0 = __floats2half2_rn(fv[r].x, fv[r].y);
                __half2 h1 = __floats2half2_rn(fv[r].z, fv[r].w);
                uint2 pkt;
                pkt.x = *reinterpret_cast<uint32_t*>(&h0);
                pkt.y = *reinterpret_cast<uint32_t*>(&h1);
                reinterpret_cast<uint2*>(g_feat)[(size_t)(row0 + r) * 256 + idx] = pkt;
            }
#pragma unroll
            for (int j = 0; j < NFAM; ++j) {
                const float4 p = sp4[j * 256 + idx];
#pragma unroll
                for (int r = 0; r < 4; ++r) {
                    float d = dot[j][r];
                    d = fmaf(p.x, fv[r].x, d);
                    d = fmaf(p.y, fv[r].y, d);
                    d = fmaf(p.z, fv[r].z, d);
                    d = fmaf(p.w, fv[r].w, d);
                    dot[j][r] = d;
                }
            }
        }
#pragma unroll
        for (int j = 0; j < NFAM; ++j) {
#pragma unroll
            for (int o = 16; o > 0; o >>= 1) pp[j] += __shfl_xor_sync(0xffffffffu, pp[j], o);
#pragma unroll
            for (int r = 0; r < 4; ++r)
#pragma unroll
                for (int o = 16; o > 0; o >>= 1)
                    dot[j][r] += __shfl_xor_sync(0xffffffffu, dot[j][r], o);
        }
        if (lane < 4) {
            const int r = lane;
            float best = pp[0] - 2.f * dot[0][r];
            int bi = 0;
#pragma unroll
            for (int j = 1; j < NFAM; ++j) {
                const float d = pp[j] - 2.f * dot[j][r];
                if (d < best) { best = d; bi = j; }
            }
            g_nearest[row0 + r] = bi;
        }
    } else if (blk < 3072) {
        // ---------------- tcvt (transpose + fp16) ----------------
        const int which = (blk < 2048) ? 0 : 1;
        const float* W = (which == 0) ? W1 : W2;
        __half* dst = (which == 0) ? g_w1t : g_w2t;
        const int b = blk - (which ? 2048 : 1024);
        const int bx = (b & 31) * 32, by = (b >> 5) * 32;

        float* t = reinterpret_cast<float*>(sp4);   // [32][33]
        const int tx = threadIdx.x & 31, ty = threadIdx.x >> 5;   // (32, 8)
#pragma unroll
        for (int j = 0; j < 4; ++j)
            t[(ty + 8 * j) * 33 + tx] = W[(size_t)(by + ty + 8 * j) * HDIM + bx + tx];
        __syncthreads();
#pragma unroll
        for (int j = 0; j < 4; ++j)
            dst[(size_t)(bx + ty + 8 * j) * HDIM + by + tx] =
                __float2half_rn(t[tx * 33 + ty + 8 * j]);
    } else {
        // ---------------- protow1 (exact fp32) ----------------
        const int b = blk - 3072;           // 0..39
        const int n = (b & 3) * 256 + threadIdx.x;
        const int j = b >> 2;               // 0..9
        const float* p = protos + j * HDIM;
        const float* w = W1 + (size_t)HDIM * HDIM + n;
        float acc = b1[n];
#pragma unroll 8
        for (int h = 0; h < HDIM; ++h) acc = fmaf(p[h], w[(size_t)h * HDIM], acc);
        g_protoW1[j * HDIM + n] = acc;
    }
}

// ---------------------------------------------------------------- FP16 GEMM
// Block tile 128x128, 8 warps 4(M)x2(N), warp tile 32x64.
// BK = 32 halves (64 B rows). K = 1024 -> 32 stages. 4-stage cp.async pipeline.
#define ROWB   80                      // 64 data bytes + 16 pad
#define TSTAGE (128 * ROWB)            // 10240
#define STAGEB (2 * TSTAGE)            // A + B
#define NSTG   4
#define GSMEM  (NSTG * STAGEB)         // 81920

template <bool FUSE1>
__global__ __launch_bounds__(256, 2) void f16_gemm_kernel(const float* __restrict__ b2,
                                                          float* __restrict__ out) {
    const __half* __restrict__ A = FUSE1 ? g_feat : g_hid;
    const __half* __restrict__ B = FUSE1 ? g_w1t : g_w2t;

    extern __shared__ char sm[];
    const uint32_t smA = smem_u32(sm);

    const int tid  = threadIdx.x;
    const int lane = tid & 31;
    const int wid  = tid >> 5;
    const int wm   = (wid & 3) * 32;     // warp M offset
    const int wn   = (wid >> 2) * 64;    // warp N offset
    const int bm   = blockIdx.y * 128;
    const int bn   = blockIdx.x * 128;

    // loader: 512 A-chunks + 512 B-chunks of 16B per stage; 2+2 per thread.
    const int rA0 = tid >> 2,         kA0 = tid & 3;
    const int rA1 = (tid + 256) >> 2, kA1 = (tid + 256) & 3;

    auto load_stage = [&](int s, int buf) {
        const int kc = s * 32;               // half offset
        const uint32_t dA = smA + buf * STAGEB;
        const uint32_t dB = dA + TSTAGE;
        cp16(dA + rA0 * ROWB + kA0 * 16, A + (size_t)(bm + rA0) * HDIM + kc + kA0 * 8);
        cp16(dA + rA1 * ROWB + kA1 * 16, A + (size_t)(bm + rA1) * HDIM + kc + kA1 * 8);
        cp16(dB + rA0 * ROWB + kA0 * 16, B + (size_t)(bn + rA0) * HDIM + kc + kA0 * 8);
        cp16(dB + rA1 * ROWB + kA1 * 16, B + (size_t)(bn + rA1) * HDIM + kc + kA1 * 8);
    };

    float acc[2][8][4];
#pragma unroll
    for (int i = 0; i < 2; ++i)
#pragma unroll
        for (int j = 0; j < 8; ++j)
#pragma unroll
            for (int k = 0; k < 4; ++k) acc[i][j][k] = 0.f;

    const uint32_t aAddr0 = smA + (wm + (lane & 15)) * ROWB + (lane >> 4) * 16;
    const uint32_t bAddr0 = smA + TSTAGE + (wn + (lane & 7) + ((lane >> 4) << 3)) * ROWB
                                + (((lane >> 3) & 1) << 4);

    load_stage(0, 0); CP_COMMIT();
    load_stage(1, 1); CP_COMMIT();
    load_stage(2, 2); CP_COMMIT();

    for (int s = 0; s < 32; ++s) {
        CP_WAIT2();
        __syncthreads();
        if (s + 3 < 32) load_stage(s + 3, (s + 3) & (NSTG - 1));
        CP_COMMIT();

        const int buf = s & (NSTG - 1);
        const uint32_t aB = aAddr0 + buf * STAGEB;
        const uint32_t bB = bAddr0 + buf * STAGEB;
#pragma unroll
        for (int ks = 0; ks < 2; ++ks) {       // 2 k-slices of 16 halves (32 B each)
            const int ko = ks * 32;
            uint32_t a[2][4];
#pragma unroll
            for (int mt = 0; mt < 2; ++mt)
                ldsm4(a[mt][0], a[mt][1], a[mt][2], a[mt][3], aB + mt * 16 * ROWB + ko);
            uint32_t b[4][4];
#pragma unroll
            for (int g = 0; g < 4; ++g)
                ldsm4(b[g][0], b[g][1], b[g][2], b[g][3], bB + g * 16 * ROWB + ko);
#pragma unroll
            for (int mt = 0; mt < 2; ++mt)
#pragma unroll
                for (int g = 0; g < 4; ++g) {
                    mma_f16(acc[mt][g * 2 + 0], a[mt][0], a[mt][1], a[mt][2], a[mt][3],
                            b[g][0], b[g][1]);
                    mma_f16(acc[mt][g * 2 + 1], a[mt][0], a[mt][1], a[mt][2], a[mt][3],
                            b[g][2], b[g][3]);
                }
        }
    }

    // ---------------- epilogue ----------------
    const int grp = lane >> 2;
    const int tig = lane & 3;
#pragma unroll
    for (int mt = 0; mt < 2; ++mt) {
        const int r0 = bm + wm + mt * 16 + grp;
        const int r1 = r0 + 8;
        const float* av0;
        const float* av1;
        if (FUSE1) {
            av0 = g_protoW1 + (size_t)g_nearest[r0] * HDIM;
            av1 = g_protoW1 + (size_t)g_nearest[r1] * HDIM;
        } else {
            av0 = b2; av1 = b2;
        }
#pragma unroll
        for (int gg = 0; gg < 8; ++gg) {
            const int col = bn + wn + (gg >> 1) * 16 + (gg & 1) * 8 + tig * 2;
            const float2 p0 = *reinterpret_cast<const float2*>(av0 + col);
            const float2 p1 = *reinterpret_cast<const float2*>(av1 + col);
            float v00 = acc[mt][gg][0] + p0.x, v01 = acc[mt][gg][1] + p0.y;
            float v10 = acc[mt][gg][2] + p1.x, v11 = acc[mt][gg][3] + p1.y;
            if (FUSE1) {
                v00 = fmaxf(v00, 0.f); v01 = fmaxf(v01, 0.f);
                v10 = fmaxf(v10, 0.f); v11 = fmaxf(v11, 0.f);
                __half2 h0 = __floats2half2_rn(v00, v01);
                __half2 h1 = __floats2half2_rn(v10, v11);
                *reinterpret_cast<__half2*>(g_hid + (size_t)r0 * HDIM + col) = h0;
                *reinterpret_cast<__half2*>(g_hid + (size_t)r1 * HDIM + col) = h1;
            } else {
                *reinterpret_cast<float2*>(out + (size_t)r0 * HDIM + col) = make_float2(v00, v01);
                *reinterpret_cast<float2*>(out + (size_t)r1 * HDIM + col) = make_float2(v10, v11);
            }
        }
    }
}

// ---------------------------------------------------------------- launch
extern "C" void kernel_launch(void* const* d_in, const int* in_sizes, int n_in,
                              void* d_out, int out_size) {
    (void)in_sizes; (void)n_in; (void)out_size;
    const float* features = (const float*)d_in[0];
    const float* protos   = (const float*)d_in[1];
    const float* W1       = (const float*)d_in[2];
    const float* b1       = (const float*)d_in[3];
    const float* W2       = (const float*)d_in[4];
    const float* b2       = (const float*)d_in[5];
    float* out = (float*)d_out;

    cudaFuncSetAttribute(f16_gemm_kernel<true>,  cudaFuncAttributeMaxDynamicSharedMemorySize, GSMEM);
    cudaFuncSetAttribute(f16_gemm_kernel<false>, cudaFuncAttributeMaxDynamicSharedMemorySize, GSMEM);

    prep_kernel<<<3112, 256>>>(features, protos, W1, b1, W2);

    dim3 grid(HDIM / 128, BATCH / 128);   // (8, 256)
    f16_gemm_kernel<true><<<grid, 256, GSMEM>>>(nullptr, nullptr);
    f16_gemm_kernel<false><<<grid, 256, GSMEM>>>(b2, out);
}

// round 11
// speedup vs baseline: 1.0012x; 1.0012x over previous
#include <cuda_runtime.h>
#include <cuda_fp16.h>
#include <cstdint>

#define BATCH 32768
#define HDIM  1024
#define NFAM  10

// ---------------------------------------------------------------- scratch
__device__ __align__(16) int     g_nearest[BATCH];
__device__ __align__(16) float   g_protoW1[NFAM * HDIM];
__device__ __align__(16) float   g_pp[NFAM];
__device__ __align__(16) __half  g_feat[(size_t)BATCH * HDIM];
__device__ __align__(16) __half  g_hid[(size_t)BATCH * HDIM];
__device__ __align__(16) __half  g_w1t[HDIM * HDIM];    // transposed
__device__ __align__(16) __half  g_w2t[HDIM * HDIM];    // transposed

// ---------------------------------------------------------------- helpers
__device__ __forceinline__ uint32_t smem_u32(const void* p) {
    uint32_t a;
    asm("{ .reg .u64 t; cvta.to.shared.u64 t, %1; cvt.u32.u64 %0, t; }" : "=r"(a) : "l"(p));
    return a;
}
__device__ __forceinline__ void cp16(uint32_t dst, const void* src) {
    asm volatile("cp.async.cg.shared.global [%0], [%1], 16;" :: "r"(dst), "l"(src) : "memory");
}
#define CP_COMMIT() asm volatile("cp.async.commit_group;" ::: "memory")
#define CP_WAIT2()  asm volatile("cp.async.wait_group 2;"  ::: "memory")

__device__ __forceinline__ void ldsm4(uint32_t& r0, uint32_t& r1, uint32_t& r2, uint32_t& r3,
                                      uint32_t addr) {
    asm volatile("ldmatrix.sync.aligned.m8n8.x4.shared.b16 {%0,%1,%2,%3}, [%4];"
                 : "=r"(r0), "=r"(r1), "=r"(r2), "=r"(r3) : "r"(addr));
}
__device__ __forceinline__ void mma_f16(float* c, uint32_t a0, uint32_t a1, uint32_t a2,
                                        uint32_t a3, uint32_t b0, uint32_t b1) {
    asm volatile("mma.sync.aligned.m16n8k16.row.col.f32.f16.f16.f32 "
                 "{%0,%1,%2,%3}, {%4,%5,%6,%7}, {%8,%9}, {%0,%1,%2,%3};"
                 : "+f"(c[0]), "+f"(c[1]), "+f"(c[2]), "+f"(c[3])
                 : "r"(a0), "r"(a1), "r"(a2), "r"(a3), "r"(b0), "r"(b1));
}

// ---------------------------------------------------------------- prep kernels
__global__ void pp_kernel(const float* __restrict__ protos) {
    const int j = threadIdx.x >> 5, lane = threadIdx.x & 31;
    if (j < NFAM) {
        float s = 0.f;
        for (int h = lane; h < HDIM; h += 32) {
            const float p = protos[j * HDIM + h];
            s = fmaf(p, p, s);
        }
#pragma unroll
        for (int o = 16; o > 0; o >>= 1) s += __shfl_xor_sync(0xffffffffu, s, o);
        if (lane == 0) g_pp[j] = s;
    }
}

// Fused fp16-convert + nearest-prototype. 2 rows/warp for low regs -> high occ.
// Grid BATCH/16, 256 threads (8 warps x 2 rows).
__global__ __launch_bounds__(256) void argcvt_kernel(const float* __restrict__ feat,
                                                     const float* __restrict__ protos) {
    __shared__ float4 sp4[NFAM * 256];   // 40 KB
    for (int i = threadIdx.x; i < NFAM * 256; i += 256)
        sp4[i] = reinterpret_cast<const float4*>(protos)[i];
    __syncthreads();

    const int warp = threadIdx.x >> 5, lane = threadIdx.x & 31;
    const int row0 = (blockIdx.x * 8 + warp) * 2;

    float dot[NFAM][2];
#pragma unroll
    for (int j = 0; j < NFAM; ++j) { dot[j][0] = 0.f; dot[j][1] = 0.f; }

    for (int t = 0; t < 8; ++t) {
        const int idx = lane + 32 * t;       // float4 index within row
        float4 fv[2];
        fv[0] = reinterpret_cast<const float4*>(feat)[(size_t)row0 * 256 + idx];
        fv[1] = reinterpret_cast<const float4*>(feat)[(size_t)(row0 + 1) * 256 + idx];

#pragma unroll
        for (int r = 0; r < 2; ++r) {
            __half2 h0 = __floats2half2_rn(fv[r].x, fv[r].y);
            __half2 h1 = __floats2half2_rn(fv[r].z, fv[r].w);
            uint2 pkt;
            pkt.x = *reinterpret_cast<uint32_t*>(&h0);
            pkt.y = *reinterpret_cast<uint32_t*>(&h1);
            reinterpret_cast<uint2*>(g_feat)[(size_t)(row0 + r) * 256 + idx] = pkt;
        }
#pragma unroll
        for (int j = 0; j < NFAM; ++j) {
            const float4 p = sp4[j * 256 + idx];
#pragma unroll
            for (int r = 0; r < 2; ++r) {
                float d = dot[j][r];
                d = fmaf(p.x, fv[r].x, d);
                d = fmaf(p.y, fv[r].y, d);
                d = fmaf(p.z, fv[r].z, d);
                d = fmaf(p.w, fv[r].w, d);
                dot[j][r] = d;
            }
        }
    }
#pragma unroll
    for (int j = 0; j < NFAM; ++j)
#pragma unroll
        for (int r = 0; r < 2; ++r)
#pragma unroll
            for (int o = 16; o > 0; o >>= 1)
                dot[j][r] += __shfl_xor_sync(0xffffffffu, dot[j][r], o);

    if (lane < 2) {
        const int r = lane;
        float best = g_pp[0] - 2.f * dot[0][r];
        int bi = 0;
#pragma unroll
        for (int j = 1; j < NFAM; ++j) {
            const float d = g_pp[j] - 2.f * dot[j][r];
            if (d < best) { best = d; bi = j; }
        }
        g_nearest[row0 + r] = bi;
    }
}

// transpose + fp16 convert: dst[n*1024+k] = half(W[k*1024+n]).  WHICH 0 -> w1t, 1 -> w2t.
template <int WHICH>
__global__ __launch_bounds__(256) void tcvt_kernel(const float* __restrict__ W) {
    __half* dst = (WHICH == 0) ? g_w1t : g_w2t;
    __shared__ float t[32][33];
    const int bx = blockIdx.x * 32, by = blockIdx.y * 32;
    const int tx = threadIdx.x, ty = threadIdx.y;   // (32, 8)
#pragma unroll
    for (int j = 0; j < 4; ++j)
        t[ty + 8 * j][tx] = W[(size_t)(by + ty + 8 * j) * HDIM + bx + tx];
    __syncthreads();
#pragma unroll
    for (int j = 0; j < 4; ++j)
        dst[(size_t)(bx + ty + 8 * j) * HDIM + by + tx] = __float2half_rn(t[tx][ty + 8 * j]);
}

// protoW1[j][n] = b1[n] + protos[j] . W1[H + :, n]   (exact fp32)
__global__ __launch_bounds__(256) void protow1_kernel(const float* __restrict__ protos,
                                                      const float* __restrict__ W1,
                                                      const float* __restrict__ b1) {
    const int n = blockIdx.x * 256 + threadIdx.x;
    const int j = blockIdx.y;
    const float* p = protos + j * HDIM;
    const float* w = W1 + (size_t)HDIM * HDIM + n;
    float acc = b1[n];
#pragma unroll 8
    for (int h = 0; h < HDIM; ++h) acc = fmaf(p[h], w[(size_t)h * HDIM], acc);
    g_protoW1[j * HDIM + n] = acc;
}

// ---------------------------------------------------------------- FP16 GEMM
// Block tile 128x128, 8 warps 4(M)x2(N), warp tile 32x64.
// BK = 32 halves (64 B rows). K = 1024 -> 32 stages. 4-stage cp.async pipeline.
#define ROWB   80                      // 64 data bytes + 16 pad
#define TSTAGE (128 * ROWB)            // 10240
#define STAGEB (2 * TSTAGE)            // A + B
#define NSTG   4
#define GSMEM  (NSTG * STAGEB)         // 81920

template <bool FUSE1>
__global__ __launch_bounds__(256, 2) void f16_gemm_kernel(const float* __restrict__ b2,
                                                          float* __restrict__ out) {
    const __half* __restrict__ A = FUSE1 ? g_feat : g_hid;
    const __half* __restrict__ B = FUSE1 ? g_w1t : g_w2t;

    extern __shared__ char sm[];
    const uint32_t smA = smem_u32(sm);

    const int tid  = threadIdx.x;
    const int lane = tid & 31;
    const int wid  = tid >> 5;
    const int wm   = (wid & 3) * 32;     // warp M offset
    const int wn   = (wid >> 2) * 64;    // warp N offset
    const int bm   = blockIdx.y * 128;
    const int bn   = blockIdx.x * 128;

    const int rA0 = tid >> 2,         kA0 = tid & 3;
    const int rA1 = (tid + 256) >> 2, kA1 = (tid + 256) & 3;

    auto load_stage = [&](int s, int buf) {
        const int kc = s * 32;               // half offset
        const uint32_t dA = smA + buf * STAGEB;
        const uint32_t dB = dA + TSTAGE;
        cp16(dA + rA0 * ROWB + kA0 * 16, A + (size_t)(bm + rA0) * HDIM + kc + kA0 * 8);
        cp16(dA + rA1 * ROWB + kA1 * 16, A + (size_t)(bm + rA1) * HDIM + kc + kA1 * 8);
        cp16(dB + rA0 * ROWB + kA0 * 16, B + (size_t)(bn + rA0) * HDIM + kc + kA0 * 8);
        cp16(dB + rA1 * ROWB + kA1 * 16, B + (size_t)(bn + rA1) * HDIM + kc + kA1 * 8);
    };

    float acc[2][8][4];
#pragma unroll
    for (int i = 0; i < 2; ++i)
#pragma unroll
        for (int j = 0; j < 8; ++j)
#pragma unroll
            for (int k = 0; k < 4; ++k) acc[i][j][k] = 0.f;

    const uint32_t aAddr0 = smA + (wm + (lane & 15)) * ROWB + (lane >> 4) * 16;
    const uint32_t bAddr0 = smA + TSTAGE + (wn + (lane & 7) + ((lane >> 4) << 3)) * ROWB
                                + (((lane >> 3) & 1) << 4);

    load_stage(0, 0); CP_COMMIT();
    load_stage(1, 1); CP_COMMIT();
    load_stage(2, 2); CP_COMMIT();

    for (int s = 0; s < 32; ++s) {
        CP_WAIT2();
        __syncthreads();
        if (s + 3 < 32) load_stage(s + 3, (s + 3) & (NSTG - 1));
        CP_COMMIT();

        const int buf = s & (NSTG - 1);
        const uint32_t aB = aAddr0 + buf * STAGEB;
        const uint32_t bB = bAddr0 + buf * STAGEB;
#pragma unroll
        for (int ks = 0; ks < 2; ++ks) {       // 2 k-slices of 16 halves (32 B each)
            const int ko = ks * 32;
            uint32_t a[2][4];
#pragma unroll
            for (int mt = 0; mt < 2; ++mt)
                ldsm4(a[mt][0], a[mt][1], a[mt][2], a[mt][3], aB + mt * 16 * ROWB + ko);
            uint32_t b[4][4];
#pragma unroll
            for (int g = 0; g < 4; ++g)
                ldsm4(b[g][0], b[g][1], b[g][2], b[g][3], bB + g * 16 * ROWB + ko);
#pragma unroll
            for (int mt = 0; mt < 2; ++mt)
#pragma unroll
                for (int g = 0; g < 4; ++g) {
                    mma_f16(acc[mt][g * 2 + 0], a[mt][0], a[mt][1], a[mt][2], a[mt][3],
                            b[g][0], b[g][1]);
                    mma_f16(acc[mt][g * 2 + 1], a[mt][0], a[mt][1], a[mt][2], a[mt][3],
                            b[g][2], b[g][3]);
                }
        }
    }

    // ---------------- epilogue ----------------
    const int grp = lane >> 2;
    const int tig = lane & 3;
#pragma unroll
    for (int mt = 0; mt < 2; ++mt) {
        const int r0 = bm + wm + mt * 16 + grp;
        const int r1 = r0 + 8;
        const float* av0;
        const float* av1;
        if (FUSE1) {
            av0 = g_protoW1 + (size_t)g_nearest[r0] * HDIM;
            av1 = g_protoW1 + (size_t)g_nearest[r1] * HDIM;
        } else {
            av0 = b2; av1 = b2;
        }
#pragma unroll
        for (int gg = 0; gg < 8; ++gg) {
            const int col = bn + wn + (gg >> 1) * 16 + (gg & 1) * 8 + tig * 2;
            const float2 p0 = *reinterpret_cast<const float2*>(av0 + col);
            const float2 p1 = *reinterpret_cast<const float2*>(av1 + col);
            float v00 = acc[mt][gg][0] + p0.x, v01 = acc[mt][gg][1] + p0.y;
            float v10 = acc[mt][gg][2] + p1.x, v11 = acc[mt][gg][3] + p1.y;
            if (FUSE1) {
                v00 = fmaxf(v00, 0.f); v01 = fmaxf(v01, 0.f);
                v10 = fmaxf(v10, 0.f); v11 = fmaxf(v11, 0.f);
                __half2 h0 = __floats2half2_rn(v00, v01);
                __half2 h1 = __floats2half2_rn(v10, v11);
                *reinterpret_cast<__half2*>(g_hid + (size_t)r0 * HDIM + col) = h0;
                *reinterpret_cast<__half2*>(g_hid + (size_t)r1 * HDIM + col) = h1;
            } else {
                *reinterpret_cast<float2*>(out + (size_t)r0 * HDIM + col) = make_float2(v00, v01);
                *reinterpret_cast<float2*>(out + (size_t)r1 * HDIM + col) = make_float2(v10, v11);
            }
        }
    }
}

// ---------------------------------------------------------------- launch
extern "C" void kernel_launch(void* const* d_in, const int* in_sizes, int n_in,
                              void* d_out, int out_size) {
    (void)in_sizes; (void)n_in; (void)out_size;
    const float* features = (const float*)d_in[0];
    const float* protos   = (const float*)d_in[1];
    const float* W1       = (const float*)d_in[2];
    const float* b1       = (const float*)d_in[3];
    const float* W2       = (const float*)d_in[4];
    const float* b2       = (const float*)d_in[5];
    float* out = (float*)d_out;

    cudaFuncSetAttribute(f16_gemm_kernel<true>,  cudaFuncAttributeMaxDynamicSharedMemorySize, GSMEM);
    cudaFuncSetAttribute(f16_gemm_kernel<false>, cudaFuncAttributeMaxDynamicSharedMemorySize, GSMEM);

    pp_kernel<<<1, 320>>>(protos);
    argcvt_kernel<<<BATCH / 16, 256>>>(features, protos);
    tcvt_kernel<0><<<dim3(32, 32), dim3(32, 8)>>>(W1);
    tcvt_kernel<1><<<dim3(32, 32), dim3(32, 8)>>>(W2);
    protow1_kernel<<<dim3(HDIM / 256, NFAM), 256>>>(protos, W1, b1);

    dim3 grid(HDIM / 128, BATCH / 128);   // (8, 256)
    f16_gemm_kernel<true><<<grid, 256, GSMEM>>>(nullptr, nullptr);
    f16_gemm_kernel<false><<<grid, 256, GSMEM>>>(b2, out);
}

// round 12
// speedup vs baseline: 1.0207x; 1.0194x over previous
#include <cuda_runtime.h>
#include <cuda_fp16.h>
#include <cstdint>

#define BATCH 32768
#define HDIM  1024
#define NFAM  10

// ---------------------------------------------------------------- scratch
__device__ __align__(16) int     g_nearest[BATCH];
__device__ __align__(16) float   g_protoW1[NFAM * HDIM];
__device__ __align__(16) __half  g_feat[(size_t)BATCH * HDIM];
__device__ __align__(16) __half  g_hid[(size_t)BATCH * HDIM];
__device__ __align__(16) __half  g_w1t[HDIM * HDIM];    // transposed
__device__ __align__(16) __half  g_w2t[HDIM * HDIM];    // transposed

// ---------------------------------------------------------------- helpers
__device__ __forceinline__ uint32_t smem_u32(const void* p) {
    uint32_t a;
    asm("{ .reg .u64 t; cvta.to.shared.u64 t, %1; cvt.u32.u64 %0, t; }" : "=r"(a) : "l"(p));
    return a;
}
__device__ __forceinline__ void cp16(uint32_t dst, const void* src) {
    asm volatile("cp.async.cg.shared.global [%0], [%1], 16;" :: "r"(dst), "l"(src) : "memory");
}
#define CP_COMMIT() asm volatile("cp.async.commit_group;" ::: "memory")
#define CP_WAIT2()  asm volatile("cp.async.wait_group 2;"  ::: "memory")

__device__ __forceinline__ void ldsm4(uint32_t& r0, uint32_t& r1, uint32_t& r2, uint32_t& r3,
                                      uint32_t addr) {
    asm volatile("ldmatrix.sync.aligned.m8n8.x4.shared.b16 {%0,%1,%2,%3}, [%4];"
                 : "=r"(r0), "=r"(r1), "=r"(r2), "=r"(r3) : "r"(addr));
}
__device__ __forceinline__ void mma_f16(float* c, uint32_t a0, uint32_t a1, uint32_t a2,
                                        uint32_t a3, uint32_t b0, uint32_t b1) {
    asm volatile("mma.sync.aligned.m16n8k16.row.col.f32.f16.f16.f32 "
                 "{%0,%1,%2,%3}, {%4,%5,%6,%7}, {%8,%9}, {%0,%1,%2,%3};"
                 : "+f"(c[0]), "+f"(c[1]), "+f"(c[2]), "+f"(c[3])
                 : "r"(a0), "r"(a1), "r"(a2), "r"(a3), "r"(b0), "r"(b1));
}

// ---------------------------------------------------------------- fused prep
// Flat grid 4136 x 256:
//   [0, 2048)    : argcvt - feat -> fp16 + nearest prototype (2 rows/warp, lean regs)
//   [2048, 4096) : tcvt   - W1 / W2 transpose + fp16
//   [4096, 4136) : protow1 - exact fp32 proto @ W1_bot + b1
__global__ __launch_bounds__(256) void prep_kernel(const float* __restrict__ feat,
                                                   const float* __restrict__ protos,
                                                   const float* __restrict__ W1,
                                                   const float* __restrict__ b1,
                                                   const float* __restrict__ W2) {
    __shared__ float4 sp4[NFAM * 256];   // 40 KB (argcvt); reused as 32x33 tile by tcvt

    const int blk = blockIdx.x;

    if (blk < 2048) {
        // ---------------- argcvt (2 rows/warp) ----------------
        for (int i = threadIdx.x; i < NFAM * 256; i += 256)
            sp4[i] = reinterpret_cast<const float4*>(protos)[i];
        __syncthreads();

        const int warp = threadIdx.x >> 5, lane = threadIdx.x & 31;
        const int row0 = (blk * 8 + warp) * 2;

        // pp[j] partial (reduced together with dots)
        float pp[NFAM];
#pragma unroll
        for (int j = 0; j < NFAM; ++j) pp[j] = 0.f;

        float dot[NFAM][2];
#pragma unroll
        for (int j = 0; j < NFAM; ++j) { dot[j][0] = 0.f; dot[j][1] = 0.f; }

        for (int t = 0; t < 8; ++t) {
            const int idx = lane + 32 * t;
            float4 fv0 = reinterpret_cast<const float4*>(feat)[(size_t)row0 * 256 + idx];
            float4 fv1 = reinterpret_cast<const float4*>(feat)[(size_t)(row0 + 1) * 256 + idx];

            {
                __half2 h0 = __floats2half2_rn(fv0.x, fv0.y);
                __half2 h1 = __floats2half2_rn(fv0.z, fv0.w);
                uint2 pkt;
                pkt.x = *reinterpret_cast<uint32_t*>(&h0);
                pkt.y = *reinterpret_cast<uint32_t*>(&h1);
                reinterpret_cast<uint2*>(g_feat)[(size_t)row0 * 256 + idx] = pkt;
                h0 = __floats2half2_rn(fv1.x, fv1.y);
                h1 = __floats2half2_rn(fv1.z, fv1.w);
                pkt.x = *reinterpret_cast<uint32_t*>(&h0);
                pkt.y = *reinterpret_cast<uint32_t*>(&h1);
                reinterpret_cast<uint2*>(g_feat)[(size_t)(row0 + 1) * 256 + idx] = pkt;
            }
#pragma unroll
            for (int j = 0; j < NFAM; ++j) {
                const float4 p = sp4[j * 256 + idx];
                pp[j] = fmaf(p.x, p.x, fmaf(p.y, p.y, fmaf(p.z, p.z, fmaf(p.w, p.w, pp[j]))));
                float d0 = dot[j][0], d1 = dot[j][1];
                d0 = fmaf(p.x, fv0.x, d0); d1 = fmaf(p.x, fv1.x, d1);
                d0 = fmaf(p.y, fv0.y, d0); d1 = fmaf(p.y, fv1.y, d1);
                d0 = fmaf(p.z, fv0.z, d0); d1 = fmaf(p.z, fv1.z, d1);
                d0 = fmaf(p.w, fv0.w, d0); d1 = fmaf(p.w, fv1.w, d1);
                dot[j][0] = d0; dot[j][1] = d1;
            }
        }
#pragma unroll
        for (int j = 0; j < NFAM; ++j) {
#pragma unroll
            for (int o = 16; o > 0; o >>= 1) {
                pp[j]     += __shfl_xor_sync(0xffffffffu, pp[j], o);
                dot[j][0] += __shfl_xor_sync(0xffffffffu, dot[j][0], o);
                dot[j][1] += __shfl_xor_sync(0xffffffffu, dot[j][1], o);
            }
        }
        if (lane < 2) {
            const int r = lane;
            float best = pp[0] - 2.f * dot[0][r];
            int bi = 0;
#pragma unroll
            for (int j = 1; j < NFAM; ++j) {
                const float d = pp[j] - 2.f * dot[j][r];
                if (d < best) { best = d; bi = j; }
            }
            g_nearest[row0 + r] = bi;
        }
    } else if (blk < 4096) {
        // ---------------- tcvt (transpose + fp16) ----------------
        const int b = blk - 2048;
        const int which = (b < 1024) ? 0 : 1;
        const float* W = (which == 0) ? W1 : W2;
        __half* dst = (which == 0) ? g_w1t : g_w2t;
        const int bb = b - which * 1024;
        const int bx = (bb & 31) * 32, by = (bb >> 5) * 32;

        float* t = reinterpret_cast<float*>(sp4);   // [32][33]
        const int tx = threadIdx.x & 31, ty = threadIdx.x >> 5;   // (32, 8)
#pragma unroll
        for (int j = 0; j < 4; ++j)
            t[(ty + 8 * j) * 33 + tx] = W[(size_t)(by + ty + 8 * j) * HDIM + bx + tx];
        __syncthreads();
#pragma unroll
        for (int j = 0; j < 4; ++j)
            dst[(size_t)(bx + ty + 8 * j) * HDIM + by + tx] =
                __float2half_rn(t[tx * 33 + ty + 8 * j]);
    } else {
        // ---------------- protow1 (exact fp32) ----------------
        const int b = blk - 4096;           // 0..39
        const int n = (b & 3) * 256 + threadIdx.x;
        const int j = b >> 2;               // 0..9
        const float* p = protos + j * HDIM;
        const float* w = W1 + (size_t)HDIM * HDIM + n;
        float acc = b1[n];
#pragma unroll 8
        for (int h = 0; h < HDIM; ++h) acc = fmaf(p[h], w[(size_t)h * HDIM], acc);
        g_protoW1[j * HDIM + n] = acc;
    }
}

// ---------------------------------------------------------------- FP16 GEMM
// Block tile 128x128, 8 warps 4(M)x2(N), warp tile 32x64.
// BK = 32 halves (64 B rows). K = 1024 -> 32 stages. 4-stage cp.async pipeline.
#define ROWB   80                      // 64 data bytes + 16 pad
#define TSTAGE (128 * ROWB)            // 10240
#define STAGEB (2 * TSTAGE)            // A + B
#define NSTG   4
#define GSMEM  (NSTG * STAGEB)         // 81920

template <bool FUSE1>
__global__ __launch_bounds__(256, 2) void f16_gemm_kernel(const float* __restrict__ b2,
                                                          float* __restrict__ out) {
    const __half* __restrict__ A = FUSE1 ? g_feat : g_hid;
    const __half* __restrict__ B = FUSE1 ? g_w1t : g_w2t;

    extern __shared__ char sm[];
    const uint32_t smA = smem_u32(sm);

    const int tid  = threadIdx.x;
    const int lane = tid & 31;
    const int wid  = tid >> 5;
    const int wm   = (wid & 3) * 32;     // warp M offset
    const int wn   = (wid >> 2) * 64;    // warp N offset
    const int bm   = blockIdx.y * 128;
    const int bn   = blockIdx.x * 128;

    const int rA0 = tid >> 2,         kA0 = tid & 3;
    const int rA1 = (tid + 256) >> 2, kA1 = (tid + 256) & 3;

    auto load_stage = [&](int s, int buf) {
        const int kc = s * 32;               // half offset
        const uint32_t dA = smA + buf * STAGEB;
        const uint32_t dB = dA + TSTAGE;
        cp16(dA + rA0 * ROWB + kA0 * 16, A + (size_t)(bm + rA0) * HDIM + kc + kA0 * 8);
        cp16(dA + rA1 * ROWB + kA1 * 16, A + (size_t)(bm + rA1) * HDIM + kc + kA1 * 8);
        cp16(dB + rA0 * ROWB + kA0 * 16, B + (size_t)(bn + rA0) * HDIM + kc + kA0 * 8);
        cp16(dB + rA1 * ROWB + kA1 * 16, B + (size_t)(bn + rA1) * HDIM + kc + kA1 * 8);
    };

    float acc[2][8][4];
#pragma unroll
    for (int i = 0; i < 2; ++i)
#pragma unroll
        for (int j = 0; j < 8; ++j)
#pragma unroll
            for (int k = 0; k < 4; ++k) acc[i][j][k] = 0.f;

    const uint32_t aAddr0 = smA + (wm + (lane & 15)) * ROWB + (lane >> 4) * 16;
    const uint32_t bAddr0 = smA + TSTAGE + (wn + (lane & 7) + ((lane >> 4) << 3)) * ROWB
                                + (((lane >> 3) & 1) << 4);

    load_stage(0, 0); CP_COMMIT();
    load_stage(1, 1); CP_COMMIT();
    load_stage(2, 2); CP_COMMIT();

    for (int s = 0; s < 32; ++s) {
        CP_WAIT2();
        __syncthreads();
        if (s + 3 < 32) load_stage(s + 3, (s + 3) & (NSTG - 1));
        CP_COMMIT();

        const int buf = s & (NSTG - 1);
        const uint32_t aB = aAddr0 + buf * STAGEB;
        const uint32_t bB = bAddr0 + buf * STAGEB;
#pragma unroll
        for (int ks = 0; ks < 2; ++ks) {       // 2 k-slices of 16 halves (32 B each)
            const int ko = ks * 32;
            uint32_t a[2][4];
#pragma unroll
            for (int mt = 0; mt < 2; ++mt)
                ldsm4(a[mt][0], a[mt][1], a[mt][2], a[mt][3], aB + mt * 16 * ROWB + ko);
            uint32_t b[4][4];
#pragma unroll
            for (int g = 0; g < 4; ++g)
                ldsm4(b[g][0], b[g][1], b[g][2], b[g][3], bB + g * 16 * ROWB + ko);
#pragma unroll
            for (int mt = 0; mt < 2; ++mt)
#pragma unroll
                for (int g = 0; g < 4; ++g) {
                    mma_f16(acc[mt][g * 2 + 0], a[mt][0], a[mt][1], a[mt][2], a[mt][3],
                            b[g][0], b[g][1]);
                    mma_f16(acc[mt][g * 2 + 1], a[mt][0], a[mt][1], a[mt][2], a[mt][3],
                            b[g][2], b[g][3]);
                }
        }
    }

    // ---------------- epilogue ----------------
    const int grp = lane >> 2;
    const int tig = lane & 3;
#pragma unroll
    for (int mt = 0; mt < 2; ++mt) {
        const int r0 = bm + wm + mt * 16 + grp;
        const int r1 = r0 + 8;
        const float* av0;
        const float* av1;
        if (FUSE1) {
            av0 = g_protoW1 + (size_t)g_nearest[r0] * HDIM;
            av1 = g_protoW1 + (size_t)g_nearest[r1] * HDIM;
        } else {
            av0 = b2; av1 = b2;
        }
#pragma unroll
        for (int gg = 0; gg < 8; ++gg) {
            const int col = bn + wn + (gg >> 1) * 16 + (gg & 1) * 8 + tig * 2;
            const float2 p0 = *reinterpret_cast<const float2*>(av0 + col);
            const float2 p1 = *reinterpret_cast<const float2*>(av1 + col);
            float v00 = acc[mt][gg][0] + p0.x, v01 = acc[mt][gg][1] + p0.y;
            float v10 = acc[mt][gg][2] + p1.x, v11 = acc[mt][gg][3] + p1.y;
            if (FUSE1) {
                v00 = fmaxf(v00, 0.f); v01 = fmaxf(v01, 0.f);
                v10 = fmaxf(v10, 0.f); v11 = fmaxf(v11, 0.f);
                __half2 h0 = __floats2half2_rn(v00, v01);
                __half2 h1 = __floats2half2_rn(v10, v11);
                *reinterpret_cast<__half2*>(g_hid + (size_t)r0 * HDIM + col) = h0;
                *reinterpret_cast<__half2*>(g_hid + (size_t)r1 * HDIM + col) = h1;
            } else {
                *reinterpret_cast<float2*>(out + (size_t)r0 * HDIM + col) = make_float2(v00, v01);
                *reinterpret_cast<float2*>(out + (size_t)r1 * HDIM + col) = make_float2(v10, v11);
            }
        }
    }
}

// ---------------------------------------------------------------- launch
extern "C" void kernel_launch(void* const* d_in, const int* in_sizes, int n_in,
                              void* d_out, int out_size) {
    (void)in_sizes; (void)n_in; (void)out_size;
    const float* features = (const float*)d_in[0];
    const float* protos   = (const float*)d_in[1];
    const float* W1       = (const float*)d_in[2];
    const float* b1       = (const float*)d_in[3];
    const float* W2       = (const float*)d_in[4];
    const float* b2       = (const float*)d_in[5];
    float* out = (float*)d_out;

    cudaFuncSetAttribute(f16_gemm_kernel<true>,  cudaFuncAttributeMaxDynamicSharedMemorySize, GSMEM);
    cudaFuncSetAttribute(f16_gemm_kernel<false>, cudaFuncAttributeMaxDynamicSharedMemorySize, GSMEM);

    prep_kernel<<<4136, 256>>>(features, protos, W1, b1, W2);

    dim3 grid(HDIM / 128, BATCH / 128);   // (8, 256)
    f16_gemm_kernel<true><<<grid, 256, GSMEM>>>(nullptr, nullptr);
    f16_gemm_kernel<false><<<grid, 256, GSMEM>>>(b2, out);
}

// round 13
// speedup vs baseline: 1.0317x; 1.0108x over previous
#include <cuda_runtime.h>
#include <cuda_fp16.h>
#include <cstdint>

#define BATCH 32768
#define HDIM  1024
#define NFAM  10

// ---------------------------------------------------------------- scratch
__device__ __align__(16) int     g_nearest[BATCH];
__device__ __align__(16) float   g_protoW1[NFAM * HDIM];
__device__ __align__(16) float   g_pp[NFAM];
__device__ __align__(16) __half  g_feat[(size_t)BATCH * HDIM];
__device__ __align__(16) __half  g_hid[(size_t)BATCH * HDIM];
__device__ __align__(16) __half  g_w1t[HDIM * HDIM];    // transposed
__device__ __align__(16) __half  g_w2t[HDIM * HDIM];    // transposed

// ---------------------------------------------------------------- helpers
__device__ __forceinline__ uint32_t smem_u32(const void* p) {
    uint32_t a;
    asm("{ .reg .u64 t; cvta.to.shared.u64 t, %1; cvt.u32.u64 %0, t; }" : "=r"(a) : "l"(p));
    return a;
}
__device__ __forceinline__ void cp16(uint32_t dst, const void* src) {
    asm volatile("cp.async.cg.shared.global [%0], [%1], 16;" :: "r"(dst), "l"(src) : "memory");
}
#define CP_COMMIT() asm volatile("cp.async.commit_group;" ::: "memory")
#define CP_WAIT2()  asm volatile("cp.async.wait_group 2;"  ::: "memory")

__device__ __forceinline__ void ldsm4(uint32_t& r0, uint32_t& r1, uint32_t& r2, uint32_t& r3,
                                      uint32_t addr) {
    asm volatile("ldmatrix.sync.aligned.m8n8.x4.shared.b16 {%0,%1,%2,%3}, [%4];"
                 : "=r"(r0), "=r"(r1), "=r"(r2), "=r"(r3) : "r"(addr));
}
__device__ __forceinline__ void mma_f16(float* c, uint32_t a0, uint32_t a1, uint32_t a2,
                                        uint32_t a3, uint32_t b0, uint32_t b1) {
    asm volatile("mma.sync.aligned.m16n8k16.row.col.f32.f16.f16.f32 "
                 "{%0,%1,%2,%3}, {%4,%5,%6,%7}, {%8,%9}, {%0,%1,%2,%3};"
                 : "+f"(c[0]), "+f"(c[1]), "+f"(c[2]), "+f"(c[3])
                 : "r"(a0), "r"(a1), "r"(a2), "r"(a3), "r"(b0), "r"(b1));
}

// ---------------------------------------------------------------- pp kernel
__global__ void pp_kernel(const float* __restrict__ protos) {
    const int j = threadIdx.x >> 5, lane = threadIdx.x & 31;
    if (j < NFAM) {
        float s = 0.f;
        for (int h = lane; h < HDIM; h += 32) {
            const float p = protos[j * HDIM + h];
            s = fmaf(p, p, s);
        }
#pragma unroll
        for (int o = 16; o > 0; o >>= 1) s += __shfl_xor_sync(0xffffffffu, s, o);
        if (lane == 0) g_pp[j] = s;
    }
}

// ---------------------------------------------------------------- fused prep
// Flat grid 3092 x 512:
//   [0, 1024)    : argcvt  - 16 warps x 2 rows = 32 rows/block, prefetched loads
//   [1024, 3072) : tcvt    - W1/W2 transpose + fp16 (one 32x32 tile per block)
//   [3072, 3092) : protow1 - exact fp32
__global__ __launch_bounds__(512) void prep_kernel(const float* __restrict__ feat,
                                                   const float* __restrict__ protos,
                                                   const float* __restrict__ W1,
                                                   const float* __restrict__ b1,
                                                   const float* __restrict__ W2) {
    __shared__ float4 sp4[NFAM * 256];   // 40 KB

    const int blk = blockIdx.x;
    const int tid = threadIdx.x;

    if (blk < 1024) {
        // ---------------- argcvt ----------------
        for (int i = tid; i < NFAM * 256; i += 512)
            sp4[i] = reinterpret_cast<const float4*>(protos)[i];
        __syncthreads();

        const int warp = tid >> 5, lane = tid & 31;
        const int row0 = (blk * 16 + warp) * 2;
        const float4* base0 = reinterpret_cast<const float4*>(feat) + (size_t)row0 * 256;
        const float4* base1 = base0 + 256;

        float dot[NFAM][2];
#pragma unroll
        for (int j = 0; j < NFAM; ++j) { dot[j][0] = 0.f; dot[j][1] = 0.f; }

        float4 c0 = base0[lane];
        float4 c1 = base1[lane];

        for (int t = 0; t < 8; ++t) {
            float4 n0, n1;
            if (t < 7) {
                n0 = base0[lane + 32 * (t + 1)];
                n1 = base1[lane + 32 * (t + 1)];
            }
            const int idx = lane + 32 * t;
            {
                __half2 h0 = __floats2half2_rn(c0.x, c0.y);
                __half2 h1 = __floats2half2_rn(c0.z, c0.w);
                uint2 pkt;
                pkt.x = *reinterpret_cast<uint32_t*>(&h0);
                pkt.y = *reinterpret_cast<uint32_t*>(&h1);
                reinterpret_cast<uint2*>(g_feat)[(size_t)row0 * 256 + idx] = pkt;
                h0 = __floats2half2_rn(c1.x, c1.y);
                h1 = __floats2half2_rn(c1.z, c1.w);
                pkt.x = *reinterpret_cast<uint32_t*>(&h0);
                pkt.y = *reinterpret_cast<uint32_t*>(&h1);
                reinterpret_cast<uint2*>(g_feat)[(size_t)(row0 + 1) * 256 + idx] = pkt;
            }
#pragma unroll
            for (int j = 0; j < NFAM; ++j) {
                const float4 p = sp4[j * 256 + idx];
                float d0 = dot[j][0], d1 = dot[j][1];
                d0 = fmaf(p.x, c0.x, d0); d1 = fmaf(p.x, c1.x, d1);
                d0 = fmaf(p.y, c0.y, d0); d1 = fmaf(p.y, c1.y, d1);
                d0 = fmaf(p.z, c0.z, d0); d1 = fmaf(p.z, c1.z, d1);
                d0 = fmaf(p.w, c0.w, d0); d1 = fmaf(p.w, c1.w, d1);
                dot[j][0] = d0; dot[j][1] = d1;
            }
            c0 = n0; c1 = n1;
        }
#pragma unroll
        for (int j = 0; j < NFAM; ++j)
#pragma unroll
            for (int o = 16; o > 0; o >>= 1) {
                dot[j][0] += __shfl_xor_sync(0xffffffffu, dot[j][0], o);
                dot[j][1] += __shfl_xor_sync(0xffffffffu, dot[j][1], o);
            }
        if (lane < 2) {
            const int r = lane;
            float best = g_pp[0] - 2.f * dot[0][r];
            int bi = 0;
#pragma unroll
            for (int j = 1; j < NFAM; ++j) {
                const float d = g_pp[j] - 2.f * dot[j][r];
                if (d < best) { best = d; bi = j; }
            }
            g_nearest[row0 + r] = bi;
        }
    } else if (blk < 3072) {
        // ---------------- tcvt (transpose + fp16), 512 threads, 32x32 tile ----------------
        const int b = blk - 1024;
        const int which = b >> 10;
        const float* W = (which == 0) ? W1 : W2;
        __half* dst = (which == 0) ? g_w1t : g_w2t;
        const int bb = b & 1023;
        const int bx = (bb & 31) * 32, by = (bb >> 5) * 32;

        float* t = reinterpret_cast<float*>(sp4);   // [32][33]
        const int tx = tid & 31, ty = tid >> 5;     // (32, 16)
#pragma unroll
        for (int j = 0; j < 2; ++j)
            t[(ty + 16 * j) * 33 + tx] = W[(size_t)(by + ty + 16 * j) * HDIM + bx + tx];
        __syncthreads();
#pragma unroll
        for (int j = 0; j < 2; ++j)
            dst[(size_t)(bx + ty + 16 * j) * HDIM + by + tx] =
                __float2half_rn(t[tx * 33 + ty + 16 * j]);
    } else {
        // ---------------- protow1 (exact fp32) ----------------
        const int b = blk - 3072;           // 0..19
        const int n = (b & 1) * 512 + tid;
        const int j = b >> 1;               // 0..9
        const float* p = protos + j * HDIM;
        const float* w = W1 + (size_t)HDIM * HDIM + n;
        float acc = b1[n];
#pragma unroll 8
        for (int h = 0; h < HDIM; ++h) acc = fmaf(p[h], w[(size_t)h * HDIM], acc);
        g_protoW1[j * HDIM + n] = acc;
    }
}

// ---------------------------------------------------------------- FP16 GEMM
// Block tile 128x128, 8 warps 4(M)x2(N), warp tile 32x64.
// BK = 32 halves (64 B rows). K = 1024 -> 32 stages. 4-stage cp.async pipeline.
#define ROWB   80                      // 64 data bytes + 16 pad
#define TSTAGE (128 * ROWB)            // 10240
#define STAGEB (2 * TSTAGE)            // A + B
#define NSTG   4
#define GSMEM  (NSTG * STAGEB)         // 81920

template <bool FUSE1>
__global__ __launch_bounds__(256, 2) void f16_gemm_kernel(const float* __restrict__ b2,
                                                          float* __restrict__ out) {
    const __half* __restrict__ A = FUSE1 ? g_feat : g_hid;
    const __half* __restrict__ B = FUSE1 ? g_w1t : g_w2t;

    extern __shared__ char sm[];
    const uint32_t smA = smem_u32(sm);

    const int tid  = threadIdx.x;
    const int lane = tid & 31;
    const int wid  = tid >> 5;
    const int wm   = (wid & 3) * 32;     // warp M offset
    const int wn   = (wid >> 2) * 64;    // warp N offset
    const int bm   = blockIdx.y * 128;
    const int bn   = blockIdx.x * 128;

    const int rA0 = tid >> 2,         kA0 = tid & 3;
    const int rA1 = (tid + 256) >> 2, kA1 = (tid + 256) & 3;

    auto load_stage = [&](int s, int buf) {
        const int kc = s * 32;               // half offset
        const uint32_t dA = smA + buf * STAGEB;
        const uint32_t dB = dA + TSTAGE;
        cp16(dA + rA0 * ROWB + kA0 * 16, A + (size_t)(bm + rA0) * HDIM + kc + kA0 * 8);
        cp16(dA + rA1 * ROWB + kA1 * 16, A + (size_t)(bm + rA1) * HDIM + kc + kA1 * 8);
        cp16(dB + rA0 * ROWB + kA0 * 16, B + (size_t)(bn + rA0) * HDIM + kc + kA0 * 8);
        cp16(dB + rA1 * ROWB + kA1 * 16, B + (size_t)(bn + rA1) * HDIM + kc + kA1 * 8);
    };

    float acc[2][8][4];
#pragma unroll
    for (int i = 0; i < 2; ++i)
#pragma unroll
        for (int j = 0; j < 8; ++j)
#pragma unroll
            for (int k = 0; k < 4; ++k) acc[i][j][k] = 0.f;

    const uint32_t aAddr0 = smA + (wm + (lane & 15)) * ROWB + (lane >> 4) * 16;
    const uint32_t bAddr0 = smA + TSTAGE + (wn + (lane & 7) + ((lane >> 4) << 3)) * ROWB
                                + (((lane >> 3) & 1) << 4);

    load_stage(0, 0); CP_COMMIT();
    load_stage(1, 1); CP_COMMIT();
    load_stage(2, 2); CP_COMMIT();

    for (int s = 0; s < 32; ++s) {
        CP_WAIT2();
        __syncthreads();
        if (s + 3 < 32) load_stage(s + 3, (s + 3) & (NSTG - 1));
        CP_COMMIT();

        const int buf = s & (NSTG - 1);
        const uint32_t aB = aAddr0 + buf * STAGEB;
        const uint32_t bB = bAddr0 + buf * STAGEB;
#pragma unroll
        for (int ks = 0; ks < 2; ++ks) {       // 2 k-slices of 16 halves (32 B each)
            const int ko = ks * 32;
            uint32_t a[2][4];
#pragma unroll
            for (int mt = 0; mt < 2; ++mt)
                ldsm4(a[mt][0], a[mt][1], a[mt][2], a[mt][3], aB + mt * 16 * ROWB + ko);
            uint32_t b[4][4];
#pragma unroll
            for (int g = 0; g < 4; ++g)
                ldsm4(b[g][0], b[g][1], b[g][2], b[g][3], bB + g * 16 * ROWB + ko);
#pragma unroll
            for (int mt = 0; mt < 2; ++mt)
#pragma unroll
                for (int g = 0; g < 4; ++g) {
                    mma_f16(acc[mt][g * 2 + 0], a[mt][0], a[mt][1], a[mt][2], a[mt][3],
                            b[g][0], b[g][1]);
                    mma_f16(acc[mt][g * 2 + 1], a[mt][0], a[mt][1], a[mt][2], a[mt][3],
                            b[g][2], b[g][3]);
                }
        }
    }

    // ---------------- epilogue ----------------
    const int grp = lane >> 2;
    const int tig = lane & 3;
#pragma unroll
    for (int mt = 0; mt < 2; ++mt) {
        const int r0 = bm + wm + mt * 16 + grp;
        const int r1 = r0 + 8;
        const float* av0;
        const float* av1;
        if (FUSE1) {
            av0 = g_protoW1 + (size_t)g_nearest[r0] * HDIM;
            av1 = g_protoW1 + (size_t)g_nearest[r1] * HDIM;
        } else {
            av0 = b2; av1 = b2;
        }
#pragma unroll
        for (int gg = 0; gg < 8; ++gg) {
            const int col = bn + wn + (gg >> 1) * 16 + (gg & 1) * 8 + tig * 2;
            const float2 p0 = *reinterpret_cast<const float2*>(av0 + col);
            const float2 p1 = *reinterpret_cast<const float2*>(av1 + col);
            float v00 = acc[mt][gg][0] + p0.x, v01 = acc[mt][gg][1] + p0.y;
            float v10 = acc[mt][gg][2] + p1.x, v11 = acc[mt][gg][3] + p1.y;
            if (FUSE1) {
                v00 = fmaxf(v00, 0.f); v01 = fmaxf(v01, 0.f);
                v10 = fmaxf(v10, 0.f); v11 = fmaxf(v11, 0.f);
                __half2 h0 = __floats2half2_rn(v00, v01);
                __half2 h1 = __floats2half2_rn(v10, v11);
                *reinterpret_cast<__half2*>(g_hid + (size_t)r0 * HDIM + col) = h0;
                *reinterpret_cast<__half2*>(g_hid + (size_t)r1 * HDIM + col) = h1;
            } else {
                *reinterpret_cast<float2*>(out + (size_t)r0 * HDIM + col) = make_float2(v00, v01);
                *reinterpret_cast<float2*>(out + (size_t)r1 * HDIM + col) = make_float2(v10, v11);
            }
        }
    }
}

// ---------------------------------------------------------------- launch
extern "C" void kernel_launch(void* const* d_in, const int* in_sizes, int n_in,
                              void* d_out, int out_size) {
    (void)in_sizes; (void)n_in; (void)out_size;
    const float* features = (const float*)d_in[0];
    const float* protos   = (const float*)d_in[1];
    const float* W1       = (const float*)d_in[2];
    const float* b1       = (const float*)d_in[3];
    const float* W2       = (const float*)d_in[4];
    const float* b2       = (const float*)d_in[5];
    float* out = (float*)d_out;

    cudaFuncSetAttribute(f16_gemm_kernel<true>,  cudaFuncAttributeMaxDynamicSharedMemorySize, GSMEM);
    cudaFuncSetAttribute(f16_gemm_kernel<false>, cudaFuncAttributeMaxDynamicSharedMemorySize, GSMEM);

    pp_kernel<<<1, 320>>>(protos);
    prep_kernel<<<3092, 512>>>(features, protos, W1, b1, W2);

    dim3 grid(HDIM / 128, BATCH / 128);   // (8, 256)
    f16_gemm_kernel<true><<<grid, 256, GSMEM>>>(nullptr, nullptr);
    f16_gemm_kernel<false><<<grid, 256, GSMEM>>>(b2, out);
}

// round 14
// speedup vs baseline: 1.0478x; 1.0156x over previous
#include <cuda_runtime.h>
#include <cuda_fp16.h>
#include <cstdint>

#define BATCH 32768
#define HDIM  1024
#define NFAM  10

// ---------------------------------------------------------------- scratch
__device__ __align__(16) int     g_nearest[BATCH];
__device__ __align__(16) float   g_protoW1[NFAM * HDIM];
__device__ __align__(16) float   g_pp[NFAM];
__device__ __align__(16) __half  g_feat[(size_t)BATCH * HDIM];
__device__ __align__(16) __half  g_hid[(size_t)BATCH * HDIM];
__device__ __align__(16) __half  g_w1t[HDIM * HDIM];    // transposed
__device__ __align__(16) __half  g_w2t[HDIM * HDIM];    // transposed

// ---------------------------------------------------------------- helpers
__device__ __forceinline__ uint32_t smem_u32(const void* p) {
    uint32_t a;
    asm("{ .reg .u64 t; cvta.to.shared.u64 t, %1; cvt.u32.u64 %0, t; }" : "=r"(a) : "l"(p));
    return a;
}
__device__ __forceinline__ void cp16(uint32_t dst, const void* src) {
    asm volatile("cp.async.cg.shared.global [%0], [%1], 16;" :: "r"(dst), "l"(src) : "memory");
}
#define CP_COMMIT() asm volatile("cp.async.commit_group;" ::: "memory")
#define CP_WAIT2()  asm volatile("cp.async.wait_group 2;"  ::: "memory")
#define CP_WAIT1()  asm volatile("cp.async.wait_group 1;"  ::: "memory")

__device__ __forceinline__ void ldsm4(uint32_t& r0, uint32_t& r1, uint32_t& r2, uint32_t& r3,
                                      uint32_t addr) {
    asm volatile("ldmatrix.sync.aligned.m8n8.x4.shared.b16 {%0,%1,%2,%3}, [%4];"
                 : "=r"(r0), "=r"(r1), "=r"(r2), "=r"(r3) : "r"(addr));
}
__device__ __forceinline__ void mma_f16(float* c, uint32_t a0, uint32_t a1, uint32_t a2,
                                        uint32_t a3, uint32_t b0, uint32_t b1) {
    asm volatile("mma.sync.aligned.m16n8k16.row.col.f32.f16.f16.f32 "
                 "{%0,%1,%2,%3}, {%4,%5,%6,%7}, {%8,%9}, {%0,%1,%2,%3};"
                 : "+f"(c[0]), "+f"(c[1]), "+f"(c[2]), "+f"(c[3])
                 : "r"(a0), "r"(a1), "r"(a2), "r"(a3), "r"(b0), "r"(b1));
}

// ---------------------------------------------------------------- pp kernel
__global__ void pp_kernel(const float* __restrict__ protos) {
    const int j = threadIdx.x >> 5, lane = threadIdx.x & 31;
    if (j < NFAM) {
        float s = 0.f;
        for (int h = lane; h < HDIM; h += 32) {
            const float p = protos[j * HDIM + h];
            s = fmaf(p, p, s);
        }
#pragma unroll
        for (int o = 16; o > 0; o >>= 1) s += __shfl_xor_sync(0xffffffffu, s, o);
        if (lane == 0) g_pp[j] = s;
    }
}

// ---------------------------------------------------------------- fused prep
// Flat grid 3092 x 512 (unchanged from R13)
__global__ __launch_bounds__(512) void prep_kernel(const float* __restrict__ feat,
                                                   const float* __restrict__ protos,
                                                   const float* __restrict__ W1,
                                                   const float* __restrict__ b1,
                                                   const float* __restrict__ W2) {
    __shared__ float4 sp4[NFAM * 256];   // 40 KB

    const int blk = blockIdx.x;
    const int tid = threadIdx.x;

    if (blk < 1024) {
        for (int i = tid; i < NFAM * 256; i += 512)
            sp4[i] = reinterpret_cast<const float4*>(protos)[i];
        __syncthreads();

        const int warp = tid >> 5, lane = tid & 31;
        const int row0 = (blk * 16 + warp) * 2;
        const float4* base0 = reinterpret_cast<const float4*>(feat) + (size_t)row0 * 256;
        const float4* base1 = base0 + 256;

        float dot[NFAM][2];
#pragma unroll
        for (int j = 0; j < NFAM; ++j) { dot[j][0] = 0.f; dot[j][1] = 0.f; }

        float4 c0 = base0[lane];
        float4 c1 = base1[lane];

        for (int t = 0; t < 8; ++t) {
            float4 n0, n1;
            if (t < 7) {
                n0 = base0[lane + 32 * (t + 1)];
                n1 = base1[lane + 32 * (t + 1)];
            }
            const int idx = lane + 32 * t;
            {
                __half2 h0 = __floats2half2_rn(c0.x, c0.y);
                __half2 h1 = __floats2half2_rn(c0.z, c0.w);
                uint2 pkt;
                pkt.x = *reinterpret_cast<uint32_t*>(&h0);
                pkt.y = *reinterpret_cast<uint32_t*>(&h1);
                reinterpret_cast<uint2*>(g_feat)[(size_t)row0 * 256 + idx] = pkt;
                h0 = __floats2half2_rn(c1.x, c1.y);
                h1 = __floats2half2_rn(c1.z, c1.w);
                pkt.x = *reinterpret_cast<uint32_t*>(&h0);
                pkt.y = *reinterpret_cast<uint32_t*>(&h1);
                reinterpret_cast<uint2*>(g_feat)[(size_t)(row0 + 1) * 256 + idx] = pkt;
            }
#pragma unroll
            for (int j = 0; j < NFAM; ++j) {
                const float4 p = sp4[j * 256 + idx];
                float d0 = dot[j][0], d1 = dot[j][1];
                d0 = fmaf(p.x, c0.x, d0); d1 = fmaf(p.x, c1.x, d1);
                d0 = fmaf(p.y, c0.y, d0); d1 = fmaf(p.y, c1.y, d1);
                d0 = fmaf(p.z, c0.z, d0); d1 = fmaf(p.z, c1.z, d1);
                d0 = fmaf(p.w, c0.w, d0); d1 = fmaf(p.w, c1.w, d1);
                dot[j][0] = d0; dot[j][1] = d1;
            }
            c0 = n0; c1 = n1;
        }
#pragma unroll
        for (int j = 0; j < NFAM; ++j)
#pragma unroll
            for (int o = 16; o > 0; o >>= 1) {
                dot[j][0] += __shfl_xor_sync(0xffffffffu, dot[j][0], o);
                dot[j][1] += __shfl_xor_sync(0xffffffffu, dot[j][1], o);
            }
        if (lane < 2) {
            const int r = lane;
            float best = g_pp[0] - 2.f * dot[0][r];
            int bi = 0;
#pragma unroll
            for (int j = 1; j < NFAM; ++j) {
                const float d = g_pp[j] - 2.f * dot[j][r];
                if (d < best) { best = d; bi = j; }
            }
            g_nearest[row0 + r] = bi;
        }
    } else if (blk < 3072) {
        const int b = blk - 1024;
        const int which = b >> 10;
        const float* W = (which == 0) ? W1 : W2;
        __half* dst = (which == 0) ? g_w1t : g_w2t;
        const int bb = b & 1023;
        const int bx = (bb & 31) * 32, by = (bb >> 5) * 32;

        float* t = reinterpret_cast<float*>(sp4);   // [32][33]
        const int tx = tid & 31, ty = tid >> 5;     // (32, 16)
#pragma unroll
        for (int j = 0; j < 2; ++j)
            t[(ty + 16 * j) * 33 + tx] = W[(size_t)(by + ty + 16 * j) * HDIM + bx + tx];
        __syncthreads();
#pragma unroll
        for (int j = 0; j < 2; ++j)
            dst[(size_t)(bx + ty + 16 * j) * HDIM + by + tx] =
                __float2half_rn(t[tx * 33 + ty + 16 * j]);
    } else {
        const int b = blk - 3072;           // 0..19
        const int n = (b & 1) * 512 + tid;
        const int j = b >> 1;               // 0..9
        const float* p = protos + j * HDIM;
        const float* w = W1 + (size_t)HDIM * HDIM + n;
        float acc = b1[n];
#pragma unroll 8
        for (int h = 0; h < HDIM; ++h) acc = fmaf(p[h], w[(size_t)h * HDIM], acc);
        g_protoW1[j * HDIM + n] = acc;
    }
}

// ---------------------------------------------------------------- FP16 GEMM
// Block tile 128x128, 8 warps 4(M)x2(N), warp tile 32x64.
// BK = 32 halves (64 B rows). 32 stages, 4-stage cp.async pipeline,
// fragment double-buffering across slices AND stage boundaries.
#define ROWB   80                      // 64 data bytes + 16 pad
#define TSTAGE (128 * ROWB)            // 10240
#define STAGEB (2 * TSTAGE)            // A + B
#define NSTG   4
#define GSMEM  (NSTG * STAGEB)         // 81920

template <bool FUSE1>
__global__ __launch_bounds__(256, 2) void f16_gemm_kernel(const float* __restrict__ b2,
                                                          float* __restrict__ out) {
    const __half* __restrict__ A = FUSE1 ? g_feat : g_hid;
    const __half* __restrict__ B = FUSE1 ? g_w1t : g_w2t;

    extern __shared__ char sm[];
    const uint32_t smA = smem_u32(sm);

    const int tid  = threadIdx.x;
    const int lane = tid & 31;
    const int wid  = tid >> 5;
    const int wm   = (wid & 3) * 32;     // warp M offset
    const int wn   = (wid >> 2) * 64;    // warp N offset
    const int bm   = blockIdx.y * 128;
    const int bn   = blockIdx.x * 128;

    const int rA0 = tid >> 2,         kA0 = tid & 3;
    const int rA1 = (tid + 256) >> 2, kA1 = (tid + 256) & 3;

    auto load_stage = [&](int s, int buf) {
        const int kc = s * 32;               // half offset
        const uint32_t dA = smA + buf * STAGEB;
        const uint32_t dB = dA + TSTAGE;
        cp16(dA + rA0 * ROWB + kA0 * 16, A + (size_t)(bm + rA0) * HDIM + kc + kA0 * 8);
        cp16(dA + rA1 * ROWB + kA1 * 16, A + (size_t)(bm + rA1) * HDIM + kc + kA1 * 8);
        cp16(dB + rA0 * ROWB + kA0 * 16, B + (size_t)(bn + rA0) * HDIM + kc + kA0 * 8);
        cp16(dB + rA1 * ROWB + kA1 * 16, B + (size_t)(bn + rA1) * HDIM + kc + kA1 * 8);
    };

    float acc[2][8][4];
#pragma unroll
    for (int i = 0; i < 2; ++i)
#pragma unroll
        for (int j = 0; j < 8; ++j)
#pragma unroll
            for (int k = 0; k < 4; ++k) acc[i][j][k] = 0.f;

    const uint32_t aAddr0 = smA + (wm + (lane & 15)) * ROWB + (lane >> 4) * 16;
    const uint32_t bAddr0 = smA + TSTAGE + (wn + (lane & 7) + ((lane >> 4) << 3)) * ROWB
                                + (((lane >> 3) & 1) << 4);

    // fragment sets: f0 = slice (s, 0), f1 = slice (s, 1)
    uint32_t a0[2][4], b0[4][4], a1[2][4], b1[4][4];

#define LDSM_SLICE(af, bf, aB, bB, ko)                                         \
    do {                                                                       \
        _Pragma("unroll")                                                      \
        for (int mt = 0; mt < 2; ++mt)                                         \
            ldsm4((af)[mt][0], (af)[mt][1], (af)[mt][2], (af)[mt][3],          \
                  (aB) + mt * 16 * ROWB + (ko));                               \
        _Pragma("unroll")                                                      \
        for (int g = 0; g < 4; ++g)                                            \
            ldsm4((bf)[g][0], (bf)[g][1], (bf)[g][2], (bf)[g][3],              \
                  (bB) + g * 16 * ROWB + (ko));                                \
    } while (0)

#define MMA_SLICE(af, bf)                                                      \
    do {                                                                       \
        _Pragma("unroll")                                                      \
        for (int mt = 0; mt < 2; ++mt)                                         \
            _Pragma("unroll")                                                  \
            for (int g = 0; g < 4; ++g) {                                      \
                mma_f16(acc[mt][g * 2 + 0], (af)[mt][0], (af)[mt][1],          \
                        (af)[mt][2], (af)[mt][3], (bf)[g][0], (bf)[g][1]);     \
                mma_f16(acc[mt][g * 2 + 1], (af)[mt][0], (af)[mt][1],          \
                        (af)[mt][2], (af)[mt][3], (bf)[g][2], (bf)[g][3]);     \
            }                                                                  \
    } while (0)

    load_stage(0, 0); CP_COMMIT();
    load_stage(1, 1); CP_COMMIT();
    load_stage(2, 2); CP_COMMIT();
    CP_WAIT2();
    __syncthreads();
    LDSM_SLICE(a0, b0, aAddr0, bAddr0, 0);

    for (int s = 0; s < 32; ++s) {
        const int buf = s & (NSTG - 1);
        const uint32_t aB = aAddr0 + buf * STAGEB;
        const uint32_t bB = bAddr0 + buf * STAGEB;

        LDSM_SLICE(a1, b1, aB, bB, 32);     // slice (s, 1) — same buffer, data ready
        MMA_SLICE(a0, b0);                  // slice (s, 0)

        if (s < 31) {
            CP_WAIT1();                     // stages <= s+1 complete
            __syncthreads();
            if (s + 3 < 32) load_stage(s + 3, (s + 3) & (NSTG - 1));
            CP_COMMIT();                    // unconditional: keeps group accounting
            const int nb = (s + 1) & (NSTG - 1);
            LDSM_SLICE(a0, b0, aAddr0 + nb * STAGEB, bAddr0 + nb * STAGEB, 0);
        }
        MMA_SLICE(a1, b1);                  // slice (s, 1), covers ldsm f0 latency
    }

    // ---------------- epilogue ----------------
    const int grp = lane >> 2;
    const int tig = lane & 3;
#pragma unroll
    for (int mt = 0; mt < 2; ++mt) {
        const int r0 = bm + wm + mt * 16 + grp;
        const int r1 = r0 + 8;
        const float* av0;
        const float* av1;
        if (FUSE1) {
            av0 = g_protoW1 + (size_t)g_nearest[r0] * HDIM;
            av1 = g_protoW1 + (size_t)g_nearest[r1] * HDIM;
        } else {
            av0 = b2; av1 = b2;
        }
#pragma unroll
        for (int gg = 0; gg < 8; ++gg) {
            const int col = bn + wn + (gg >> 1) * 16 + (gg & 1) * 8 + tig * 2;
            const float2 p0 = *reinterpret_cast<const float2*>(av0 + col);
            const float2 p1 = *reinterpret_cast<const float2*>(av1 + col);
            float v00 = acc[mt][gg][0] + p0.x, v01 = acc[mt][gg][1] + p0.y;
            float v10 = acc[mt][gg][2] + p1.x, v11 = acc[mt][gg][3] + p1.y;
            if (FUSE1) {
                v00 = fmaxf(v00, 0.f); v01 = fmaxf(v01, 0.f);
                v10 = fmaxf(v10, 0.f); v11 = fmaxf(v11, 0.f);
                __half2 h0 = __floats2half2_rn(v00, v01);
                __half2 h1 = __floats2half2_rn(v10, v11);
                *reinterpret_cast<__half2*>(g_hid + (size_t)r0 * HDIM + col) = h0;
                *reinterpret_cast<__half2*>(g_hid + (size_t)r1 * HDIM + col) = h1;
            } else {
                *reinterpret_cast<float2*>(out + (size_t)r0 * HDIM + col) = make_float2(v00, v01);
                *reinterpret_cast<float2*>(out + (size_t)r1 * HDIM + col) = make_float2(v10, v11);
            }
        }
    }
}

// ---------------------------------------------------------------- launch
extern "C" void kernel_launch(void* const* d_in, const int* in_sizes, int n_in,
                              void* d_out, int out_size) {
    (void)in_sizes; (void)n_in; (void)out_size;
    const float* features = (const float*)d_in[0];
    const float* protos   = (const float*)d_in[1];
    const float* W1       = (const float*)d_in[2];
    const float* b1       = (const float*)d_in[3];
    const float* W2       = (const float*)d_in[4];
    const float* b2       = (const float*)d_in[5];
    float* out = (float*)d_out;

    cudaFuncSetAttribute(f16_gemm_kernel<true>,  cudaFuncAttributeMaxDynamicSharedMemorySize, GSMEM);
    cudaFuncSetAttribute(f16_gemm_kernel<false>, cudaFuncAttributeMaxDynamicSharedMemorySize, GSMEM);

    pp_kernel<<<1, 320>>>(protos);
    prep_kernel<<<3092, 512>>>(features, protos, W1, b1, W2);

    dim3 grid(HDIM / 128, BATCH / 128);   // (8, 256)
    f16_gemm_kernel<true><<<grid, 256, GSMEM>>>(nullptr, nullptr);
    f16_gemm_kernel<false><<<grid, 256, GSMEM>>>(b2, out);
}